// round 1
// baseline (speedup 1.0000x reference)
#include <cuda_runtime.h>

#define BB 32
#define CC 512
#define LL 1024

// Scratch (static device globals -- allocation-free per harness rules)
__device__ float g_act[BB*CC*LL];                 // conv output [B,C,L]
__device__ unsigned int g_xq[BB*LL*(CC/4)];       // packed int8 activations [B,L,C/4]
__device__ float g_arecip[BB*LL];                 // per-token absmax/127
__device__ float g_mean[CC];
__device__ float g_rstd[CC];
__device__ float g_wrecip_d;                      // clip(mean|w|, 1e-5)
__device__ float g_wscale_d;                      // 1/clip(mean|w|, 1e-5)
__device__ unsigned int g_wq[CC*(CC/4)];          // packed ternary weights [O,C/4]

__device__ __forceinline__ float gelu_f(float v){
    return 0.5f*v*(1.0f + erff(v*0.70710678118654752440f));
}

// ---------------------------------------------------------------------------
// K1: Conv1d (k=3, pad=1) as implicit GEMM, fp32. Block tile 64(c) x 64(l),
// thread tile 4x4, K-loop over input channels in chunks of 16.
// ---------------------------------------------------------------------------
__global__ __launch_bounds__(256) void conv_kernel(const float* __restrict__ x,
                                                   const float* __restrict__ w,
                                                   const float* __restrict__ bias){
    const int l0 = blockIdx.x * 64;
    const int c0 = blockIdx.y * 64;
    const int b  = blockIdx.z;
    const int tid = threadIdx.x;
    const int tx = tid & 15;   // l sub-tile (4 consecutive l per thread)
    const int ty = tid >> 4;   // c sub-tile

    __shared__ float xs[16][66];   // x[b][i0+ii][l0-1 .. l0+64]
    __shared__ float ws[48][64];   // w[c0+cc][i0+ii][k] at ws[ii*3+k][cc]

    float acc[4][4];
    #pragma unroll
    for (int i=0;i<4;i++){
        #pragma unroll
        for (int j=0;j<4;j++) acc[i][j]=0.f;
    }

    for (int i0 = 0; i0 < CC; i0 += 16){
        for (int idx = tid; idx < 16*66; idx += 256){
            int ii = idx / 66, p = idx % 66;
            int gl = l0 - 1 + p;
            float v = 0.f;
            if (gl >= 0 && gl < LL) v = x[(b*CC + i0 + ii)*LL + gl];
            xs[ii][p] = v;
        }
        for (int idx = tid; idx < 64*48; idx += 256){
            int cc2 = idx / 48, r = idx % 48;
            ws[r][cc2] = w[(c0+cc2)*(CC*3) + i0*3 + r];
        }
        __syncthreads();
        #pragma unroll
        for (int ii = 0; ii < 16; ii++){
            float xf[6];
            #pragma unroll
            for (int j=0;j<6;j++) xf[j] = xs[ii][tx*4 + j];
            #pragma unroll
            for (int k=0;k<3;k++){
                const float4 wv = *(const float4*)&ws[ii*3+k][ty*4];
                #pragma unroll
                for (int jj=0;jj<4;jj++){
                    float xv = xf[jj+k];
                    acc[0][jj] += wv.x*xv;
                    acc[1][jj] += wv.y*xv;
                    acc[2][jj] += wv.z*xv;
                    acc[3][jj] += wv.w*xv;
                }
            }
        }
        __syncthreads();
    }
    #pragma unroll
    for (int ci=0; ci<4; ci++){
        int c = c0 + ty*4 + ci;
        float bv = bias[c];
        float4 st;
        st.x = acc[ci][0]+bv; st.y = acc[ci][1]+bv;
        st.z = acc[ci][2]+bv; st.w = acc[ci][3]+bv;
        *(float4*)&g_act[(b*CC + c)*LL + l0 + tx*4] = st;
    }
}

// ---------------------------------------------------------------------------
// K2: BatchNorm statistics -- one block per channel (deterministic order)
// ---------------------------------------------------------------------------
__global__ __launch_bounds__(256) void bnstats_kernel(){
    const int c = blockIdx.x;
    const int tid = threadIdx.x;
    float s = 0.f, ss = 0.f;
    for (int idx = tid; idx < BB*LL; idx += 256){
        int b = idx >> 10, l = idx & (LL-1);
        float v = g_act[(b*CC + c)*LL + l];
        s += v; ss += v*v;
    }
    __shared__ float sa[256], sb[256];
    sa[tid]=s; sb[tid]=ss;
    __syncthreads();
    for (int off=128; off>0; off>>=1){
        if (tid < off){ sa[tid]+=sa[tid+off]; sb[tid]+=sb[tid+off]; }
        __syncthreads();
    }
    if (tid==0){
        float m = sa[0]*(1.0f/(BB*LL));
        float var = sb[0]*(1.0f/(BB*LL)) - m*m;
        g_mean[c]=m;
        g_rstd[c]=rsqrtf(var + 1e-5f);
    }
}

// ---------------------------------------------------------------------------
// K3: weight absmean (single block, deterministic)
// ---------------------------------------------------------------------------
__global__ __launch_bounds__(256) void wabs_kernel(const float* __restrict__ pw){
    const int tid = threadIdx.x;
    float s=0.f;
    for (int idx=tid; idx<CC*CC; idx+=256) s += fabsf(pw[idx]);
    __shared__ float sa[256];
    sa[tid]=s; __syncthreads();
    for (int off=128; off>0; off>>=1){
        if (tid<off) sa[tid]+=sa[tid+off];
        __syncthreads();
    }
    if (tid==0){
        float m = sa[0]*(1.0f/(CC*CC));
        m = fmaxf(m, 1e-5f);
        g_wrecip_d = m;
        g_wscale_d = 1.0f/m;
    }
}

// ---------------------------------------------------------------------------
// K4: ternary quantize + pack proj_w to int8x4
// ---------------------------------------------------------------------------
__global__ __launch_bounds__(256) void wpack_kernel(const float* __restrict__ pw){
    const int p = blockIdx.x*256 + threadIdx.x;   // 65536 packs
    const float sc = g_wscale_d;
    unsigned int packv = 0;
    #pragma unroll
    for (int j=0;j<4;j++){
        float t = rintf(pw[p*4+j]*sc);
        t = fmaxf(-1.f, fminf(1.f, t));
        int v = (int)t;
        packv |= ((unsigned int)(v & 0xFF)) << (8*j);
    }
    g_wq[p] = packv;
}

// ---------------------------------------------------------------------------
// K5: BN + GELU + per-token absmax + int8 quantize/pack into [B,L,C/4]
// Block = (b, 32 consecutive l). 256 threads = 32 lanes(l) x 8 channel slots.
// ---------------------------------------------------------------------------
__global__ __launch_bounds__(256) void quant_kernel(const float* __restrict__ gamma,
                                                    const float* __restrict__ beta){
    const int b  = blockIdx.y;
    const int l0 = blockIdx.x*32;
    const int tid = threadIdx.x;
    const int lane = tid & 31, cs = tid >> 5;
    const int l = l0 + lane;

    __shared__ float red[8][32];
    __shared__ float sscale[32];

    float m = 0.f;
    for (int c = cs; c < CC; c += 8){
        float a = g_act[(b*CC + c)*LL + l];
        float y = (a - g_mean[c])*g_rstd[c]*gamma[c] + beta[c];
        m = fmaxf(m, fabsf(gelu_f(y)));
    }
    red[cs][lane] = m;
    __syncthreads();
    if (tid < 32){
        float mm = red[0][tid];
        #pragma unroll
        for (int j=1;j<8;j++) mm = fmaxf(mm, red[j][tid]);
        float am = fmaxf(mm, 1e-5f);
        sscale[tid] = 127.0f/am;
        g_arecip[b*LL + l0 + tid] = am * (1.0f/127.0f);
    }
    __syncthreads();
    const float scl = sscale[lane];
    for (int cg = cs; cg < CC/4; cg += 8){
        unsigned int packv = 0;
        #pragma unroll
        for (int j=0;j<4;j++){
            int c = cg*4 + j;
            float a = g_act[(b*CC + c)*LL + l];
            float y = (a - g_mean[c])*g_rstd[c]*gamma[c] + beta[c];
            float g = gelu_f(y);
            int v = (int)rintf(g*scl);
            v = max(-128, min(127, v));
            packv |= ((unsigned int)(v & 0xFF)) << (8*j);
        }
        g_xq[(b*LL + l)*(CC/4) + cg] = packv;
    }
}

// ---------------------------------------------------------------------------
// K6: int8 ternary matmul (dp4a, exact) + dequant + GELU + residual
// Block tile 64 tokens x 64 outputs, thread tile 4x4, K=512 in 2 chunks.
// ---------------------------------------------------------------------------
__global__ __launch_bounds__(256) void matmul_kernel(const float* __restrict__ xin,
                                                     float* __restrict__ out){
    const int tok0 = blockIdx.x*64;
    const int o0   = blockIdx.y*64;
    const int b    = tok0 >> 10;
    const int lbase = tok0 & (LL-1);
    const int tid = threadIdx.x;
    const int tx = tid & 15, ty = tid >> 4;

    __shared__ unsigned int xs[64][65];
    __shared__ unsigned int wsm[64][65];

    int acc[4][4];
    #pragma unroll
    for (int i=0;i<4;i++){
        #pragma unroll
        for (int j=0;j<4;j++) acc[i][j]=0;
    }

    for (int kc = 0; kc < 2; kc++){
        const int k0 = kc*64;
        for (int idx = tid; idx < 64*64; idx += 256){
            int t = idx >> 6, k = idx & 63;
            xs[t][k] = g_xq[(tok0 + t)*(CC/4) + k0 + k];
        }
        for (int idx = tid; idx < 64*64; idx += 256){
            int o = idx >> 6, k = idx & 63;
            wsm[o][k] = g_wq[(o0 + o)*(CC/4) + k0 + k];
        }
        __syncthreads();
        #pragma unroll 8
        for (int kk = 0; kk < 64; kk++){
            int xf[4], wf[4];
            #pragma unroll
            for (int j=0;j<4;j++) xf[j] = (int)xs[tx*4+j][kk];
            #pragma unroll
            for (int j=0;j<4;j++) wf[j] = (int)wsm[ty*4+j][kk];
            #pragma unroll
            for (int oo=0;oo<4;oo++){
                #pragma unroll
                for (int tt=0;tt<4;tt++)
                    acc[oo][tt] = __dp4a(xf[tt], wf[oo], acc[oo][tt]);
            }
        }
        __syncthreads();
    }

    const float wr = g_wrecip_d;
    float ar[4];
    #pragma unroll
    for (int tt=0;tt<4;tt++) ar[tt] = g_arecip[tok0 + tx*4 + tt];

    #pragma unroll
    for (int oo=0;oo<4;oo++){
        int o = o0 + ty*4 + oo;
        const float4 rx = *(const float4*)&xin[(b*CC + o)*LL + lbase + tx*4];
        float4 st;
        st.x = gelu_f((float)acc[oo][0]*ar[0]*wr) + rx.x;
        st.y = gelu_f((float)acc[oo][1]*ar[1]*wr) + rx.y;
        st.z = gelu_f((float)acc[oo][2]*ar[2]*wr) + rx.z;
        st.w = gelu_f((float)acc[oo][3]*ar[3]*wr) + rx.w;
        *(float4*)&out[(b*CC + o)*LL + lbase + tx*4] = st;
    }
}

// ---------------------------------------------------------------------------
extern "C" void kernel_launch(void* const* d_in, const int* in_sizes, int n_in,
                              void* d_out, int out_size){
    const float* x      = (const float*)d_in[0];
    const float* conv_w = (const float*)d_in[1];
    const float* conv_b = (const float*)d_in[2];
    const float* gamma  = (const float*)d_in[3];
    const float* beta   = (const float*)d_in[4];
    const float* proj_w = (const float*)d_in[5];
    float* out = (float*)d_out;

    conv_kernel<<<dim3(16,8,32), 256>>>(x, conv_w, conv_b);
    bnstats_kernel<<<512, 256>>>();
    wabs_kernel<<<1, 256>>>(proj_w);
    wpack_kernel<<<256, 256>>>(proj_w);
    quant_kernel<<<dim3(32,32), 256>>>(gamma, beta);
    matmul_kernel<<<dim3(512,8), 256>>>(x, out);
}

// round 3
// speedup vs baseline: 4.7330x; 4.7330x over previous
#include <cuda_runtime.h>
#include <cuda_fp16.h>
#include <cstdint>

#define BB 32
#define CC 512
#define LL 1024
#define LPAD (LL + 2)

// ---------------------------------------------------------------------------
// Scratch (static device globals -- allocation-free per harness rules)
// ---------------------------------------------------------------------------
__device__ float g_act[BB*CC*LL];                   // conv output [B,C,L]
__device__ unsigned int g_xq[BB*LL*(CC/4)];         // packed int8 activations [B,L,C/4]
__device__ float g_arecip[BB*LL];                   // per-token absmax/127
__device__ float g_mean[CC];
__device__ float g_rstd[CC];
__device__ float g_wrecip_d;
__device__ float g_wscale_d;
__device__ unsigned int g_wq[CC*(CC/4)];            // packed ternary weights [O,C/4]

// fp16 split operands for tensor-core conv
__device__ __half g_xhiT[BB*LPAD*CC];               // x transposed [b][l+1][i], hi
__device__ __half g_xloT[BB*LPAD*CC];               // lo
__device__ __half g_whi[3*CC*CC];                   // w [tap][c][i], hi
__device__ __half g_wlo[3*CC*CC];                   // lo

__device__ __forceinline__ float gelu_f(float v){
    return 0.5f*v*(1.0f + erff(v*0.70710678118654752440f));
}

__device__ __forceinline__ uint32_t smem_to_u32(const void* smem_ptr) {
    uint32_t addr;
    asm("{ .reg .u64 tmp; cvta.to.shared.u64 tmp, %1; cvt.u32.u64 %0, tmp; }"
        : "=r"(addr) : "l"(smem_ptr));
    return addr;
}

#define CP_ASYNC16(dst_u32, src_ptr) \
    asm volatile("cp.async.cg.shared.global [%0], [%1], 16;" \
        :: "r"(dst_u32), "l"(src_ptr))
#define CP_COMMIT() asm volatile("cp.async.commit_group;" ::: "memory")
#define CP_WAIT1()  asm volatile("cp.async.wait_group 1;" ::: "memory")
#define CP_WAIT0()  asm volatile("cp.async.wait_group 0;" ::: "memory")

#define LDSM4(r0,r1,r2,r3,addr) \
    asm volatile("ldmatrix.sync.aligned.m8n8.x4.shared.b16 {%0,%1,%2,%3}, [%4];" \
        : "=r"(r0),"=r"(r1),"=r"(r2),"=r"(r3) : "r"(addr))

#define MMA16816(c, a, b0, b1) \
    asm volatile("mma.sync.aligned.m16n8k16.row.col.f32.f16.f16.f32 " \
        "{%0,%1,%2,%3}, {%4,%5,%6,%7}, {%8,%9}, {%0,%1,%2,%3};" \
        : "+f"((c)[0]),"+f"((c)[1]),"+f"((c)[2]),"+f"((c)[3]) \
        : "r"((a)[0]),"r"((a)[1]),"r"((a)[2]),"r"((a)[3]), "r"(b0),"r"(b1))

// ---------------------------------------------------------------------------
// P1: transpose + fp16 split of x:  x[b][i][l] -> x_T[b][l+1][i] (hi, lo)
// ---------------------------------------------------------------------------
__global__ __launch_bounds__(256) void prep_x_kernel(const float* __restrict__ x){
    __shared__ float ts[32][33];
    const int b  = blockIdx.z;
    const int i0 = blockIdx.y*32;
    const int l0 = blockIdx.x*32;
    const int tx = threadIdx.x & 31, ty = threadIdx.x >> 5;
    #pragma unroll
    for (int ii = ty; ii < 32; ii += 8)
        ts[ii][tx] = x[((size_t)b*CC + i0 + ii)*LL + l0 + tx];
    __syncthreads();
    #pragma unroll
    for (int ll = ty; ll < 32; ll += 8){
        float v = ts[tx][ll];
        __half hi = __float2half(v);
        __half lo = __float2half(v - __half2float(hi));
        size_t o = ((size_t)b*LPAD + l0 + ll + 1)*CC + i0 + tx;
        g_xhiT[o] = hi;
        g_xloT[o] = lo;
    }
}

// zero halo rows l=0 and l=LPAD-1
__global__ __launch_bounds__(256) void pad_x_kernel(){
    int idx = blockIdx.x*256 + threadIdx.x;      // 32*2*512 = 32768
    int b = idx >> 10, r = (idx >> 9) & 1, i = idx & 511;
    size_t o = ((size_t)b*LPAD + (r ? LPAD-1 : 0))*CC + i;
    g_xhiT[o] = __float2half(0.f);
    g_xloT[o] = __float2half(0.f);
}

// P2: conv_w [c][i][3] -> g_whi/g_wlo [tap][c][i] fp16 split
__global__ __launch_bounds__(256) void prep_w_kernel(const float* __restrict__ w){
    int idx = blockIdx.x*256 + threadIdx.x;      // 262144
    int c = idx >> 9, i = idx & 511;
    #pragma unroll
    for (int k = 0; k < 3; k++){
        float v = w[((size_t)c*CC + i)*3 + k];
        __half hi = __float2half(v);
        __half lo = __float2half(v - __half2float(hi));
        size_t o = ((size_t)k*CC + c)*CC + i;
        g_whi[o] = hi;
        g_wlo[o] = lo;
    }
}

// ---------------------------------------------------------------------------
// K1: Conv1d as fp16-split HMMA GEMM (mma.sync.m16n8k16).
// Block: 128 c x 128 l, 8 warps (2c x 4l), warp tile 64x32.
// K-loop: 3 taps x 16 chunks of K=32; per step compute hihi+hilo+lohi.
// SMEM: 4 tiles (Ahi,Alo,Bhi,Blo) of [128 rows x 32 fp16], 80B padded rows,
// double buffered = 81920 B dynamic.
// ---------------------------------------------------------------------------
#define TILE_B 10240                // 128 * 80
#define STAGE_B (4*TILE_B)          // 40960
#define CONV_SMEM (2*STAGE_B)       // 81920

__global__ __launch_bounds__(256) void conv_mma_kernel(const float* __restrict__ bias){
    extern __shared__ char smem[];
    const uint32_t sbase = smem_to_u32(smem);
    const int tid = threadIdx.x;
    const int lane = tid & 31, wid = tid >> 5;
    const int wc = wid & 1, wl = wid >> 1;
    const int l0 = blockIdx.x * 128;
    const int c0 = blockIdx.y * 128;
    const int b  = blockIdx.z;

    // per-thread cp.async coords: rows rowe and rowe+64, 16B chunk chk
    const int rowe = tid >> 2;
    const int chk  = tid & 3;
    const uint32_t dstoff = (uint32_t)(rowe*80 + chk*16);

    float acc[4][4][4];
    #pragma unroll
    for (int i=0;i<4;i++)
        #pragma unroll
        for (int j=0;j<4;j++)
            #pragma unroll
            for (int q=0;q<4;q++) acc[i][j][q]=0.f;

    // ---- issue loads for step s into stage ----
    #define ISSUE(s, stage) do { \
        const int tap_ = (s) >> 4, kc_ = (s) & 15; \
        const uint32_t st_ = sbase + (stage)*STAGE_B; \
        const size_t koff_ = (size_t)(kc_*32 + chk*8); \
        const size_t aoff_ = ((size_t)(tap_*CC) + c0)*CC + koff_; \
        const size_t boff_ = ((size_t)b*LPAD + l0 + tap_)*CC + koff_; \
        CP_ASYNC16(st_ + 0*TILE_B + dstoff,           g_whi  + aoff_ + (size_t)rowe*CC); \
        CP_ASYNC16(st_ + 0*TILE_B + dstoff + 64*80,   g_whi  + aoff_ + (size_t)(rowe+64)*CC); \
        CP_ASYNC16(st_ + 1*TILE_B + dstoff,           g_wlo  + aoff_ + (size_t)rowe*CC); \
        CP_ASYNC16(st_ + 1*TILE_B + dstoff + 64*80,   g_wlo  + aoff_ + (size_t)(rowe+64)*CC); \
        CP_ASYNC16(st_ + 2*TILE_B + dstoff,           g_xhiT + boff_ + (size_t)rowe*CC); \
        CP_ASYNC16(st_ + 2*TILE_B + dstoff + 64*80,   g_xhiT + boff_ + (size_t)(rowe+64)*CC); \
        CP_ASYNC16(st_ + 3*TILE_B + dstoff,           g_xloT + boff_ + (size_t)rowe*CC); \
        CP_ASYNC16(st_ + 3*TILE_B + dstoff + 64*80,   g_xloT + boff_ + (size_t)(rowe+64)*CC); \
    } while(0)

    ISSUE(0, 0);
    CP_COMMIT();

    for (int s = 0; s < 48; s++){
        const int nx = s + 1;
        if (nx < 48){
            ISSUE(nx, nx & 1);
            CP_COMMIT();
            CP_WAIT1();
        } else {
            CP_WAIT0();
        }
        __syncthreads();

        const uint32_t st = sbase + (s & 1)*STAGE_B;
        #pragma unroll
        for (int kh = 0; kh < 2; kh++){
            const uint32_t colb = (uint32_t)(kh*32 + (lane >> 4)*16);
            uint32_t ahi[4][4], alo[4][4];
            #pragma unroll
            for (int mf = 0; mf < 4; mf++){
                const uint32_t r = (uint32_t)(wc*64 + mf*16 + (lane & 15));
                const uint32_t ad = st + r*80 + colb;
                LDSM4(ahi[mf][0],ahi[mf][1],ahi[mf][2],ahi[mf][3], ad);
                LDSM4(alo[mf][0],alo[mf][1],alo[mf][2],alo[mf][3], ad + 1*TILE_B);
            }
            uint32_t bhi[4][2], blo[4][2];
            #pragma unroll
            for (int g = 0; g < 2; g++){
                const uint32_t r = (uint32_t)(wl*32 + g*16 + (lane & 15));
                const uint32_t bd = st + 2*TILE_B + r*80 + colb;
                uint32_t t0,t1,t2,t3;
                LDSM4(t0,t1,t2,t3, bd);
                bhi[g*2][0]=t0; bhi[g*2+1][0]=t1; bhi[g*2][1]=t2; bhi[g*2+1][1]=t3;
                LDSM4(t0,t1,t2,t3, bd + 1*TILE_B);
                blo[g*2][0]=t0; blo[g*2+1][0]=t1; blo[g*2][1]=t2; blo[g*2+1][1]=t3;
            }
            #pragma unroll
            for (int mf = 0; mf < 4; mf++){
                #pragma unroll
                for (int nf = 0; nf < 4; nf++){
                    MMA16816(acc[mf][nf], ahi[mf], bhi[nf][0], bhi[nf][1]);
                    MMA16816(acc[mf][nf], ahi[mf], blo[nf][0], blo[nf][1]);
                    MMA16816(acc[mf][nf], alo[mf], bhi[nf][0], bhi[nf][1]);
                }
            }
        }
        __syncthreads();
    }

    // ---- epilogue: bias + store ----
    const int lcol = l0 + wl*32 + (lane & 3)*2;
    #pragma unroll
    for (int mf = 0; mf < 4; mf++){
        const int rbase = c0 + wc*64 + mf*16 + (lane >> 2);
        #pragma unroll
        for (int half = 0; half < 2; half++){
            const int c = rbase + half*8;
            const float bv = bias[c];
            float* dst = &g_act[((size_t)b*CC + c)*LL + lcol];
            #pragma unroll
            for (int nf = 0; nf < 4; nf++){
                float2 v;
                v.x = acc[mf][nf][half*2+0] + bv;
                v.y = acc[mf][nf][half*2+1] + bv;
                *(float2*)(dst + nf*8) = v;
            }
        }
    }
}

// ---------------------------------------------------------------------------
// K2: BatchNorm statistics -- one block per channel (deterministic order)
// ---------------------------------------------------------------------------
__global__ __launch_bounds__(256) void bnstats_kernel(){
    const int c = blockIdx.x;
    const int tid = threadIdx.x;
    float s = 0.f, ss = 0.f;
    for (int idx = tid; idx < BB*LL; idx += 256){
        int b = idx >> 10, l = idx & (LL-1);
        float v = g_act[(b*CC + c)*LL + l];
        s += v; ss += v*v;
    }
    __shared__ float sa[256], sb[256];
    sa[tid]=s; sb[tid]=ss;
    __syncthreads();
    for (int off=128; off>0; off>>=1){
        if (tid < off){ sa[tid]+=sa[tid+off]; sb[tid]+=sb[tid+off]; }
        __syncthreads();
    }
    if (tid==0){
        float m = sa[0]*(1.0f/(BB*LL));
        float var = sb[0]*(1.0f/(BB*LL)) - m*m;
        g_mean[c]=m;
        g_rstd[c]=rsqrtf(var + 1e-5f);
    }
}

// ---------------------------------------------------------------------------
// K3: weight absmean (single block, deterministic)
// ---------------------------------------------------------------------------
__global__ __launch_bounds__(256) void wabs_kernel(const float* __restrict__ pw){
    const int tid = threadIdx.x;
    float s=0.f;
    for (int idx=tid; idx<CC*CC; idx+=256) s += fabsf(pw[idx]);
    __shared__ float sa[256];
    sa[tid]=s; __syncthreads();
    for (int off=128; off>0; off>>=1){
        if (tid<off) sa[tid]+=sa[tid+off];
        __syncthreads();
    }
    if (tid==0){
        float m = sa[0]*(1.0f/(CC*CC));
        m = fmaxf(m, 1e-5f);
        g_wrecip_d = m;
        g_wscale_d = 1.0f/m;
    }
}

// ---------------------------------------------------------------------------
// K4: ternary quantize + pack proj_w to int8x4
// ---------------------------------------------------------------------------
__global__ __launch_bounds__(256) void wpack_kernel(const float* __restrict__ pw){
    const int p = blockIdx.x*256 + threadIdx.x;
    const float sc = g_wscale_d;
    unsigned int packv = 0;
    #pragma unroll
    for (int j=0;j<4;j++){
        float t = rintf(pw[p*4+j]*sc);
        t = fmaxf(-1.f, fminf(1.f, t));
        int v = (int)t;
        packv |= ((unsigned int)(v & 0xFF)) << (8*j);
    }
    g_wq[p] = packv;
}

// ---------------------------------------------------------------------------
// K5: BN + GELU + per-token absmax + int8 quantize/pack into [B,L,C/4]
// ---------------------------------------------------------------------------
__global__ __launch_bounds__(256) void quant_kernel(const float* __restrict__ gamma,
                                                    const float* __restrict__ beta){
    const int b  = blockIdx.y;
    const int l0 = blockIdx.x*32;
    const int tid = threadIdx.x;
    const int lane = tid & 31, cs = tid >> 5;
    const int l = l0 + lane;

    __shared__ float red[8][32];
    __shared__ float sscale[32];

    float m = 0.f;
    for (int c = cs; c < CC; c += 8){
        float a = g_act[(b*CC + c)*LL + l];
        float y = (a - g_mean[c])*g_rstd[c]*gamma[c] + beta[c];
        m = fmaxf(m, fabsf(gelu_f(y)));
    }
    red[cs][lane] = m;
    __syncthreads();
    if (tid < 32){
        float mm = red[0][tid];
        #pragma unroll
        for (int j=1;j<8;j++) mm = fmaxf(mm, red[j][tid]);
        float am = fmaxf(mm, 1e-5f);
        sscale[tid] = 127.0f/am;
        g_arecip[b*LL + l0 + tid] = am * (1.0f/127.0f);
    }
    __syncthreads();
    const float scl = sscale[lane];
    for (int cg = cs; cg < CC/4; cg += 8){
        unsigned int packv = 0;
        #pragma unroll
        for (int j=0;j<4;j++){
            int c = cg*4 + j;
            float a = g_act[(b*CC + c)*LL + l];
            float y = (a - g_mean[c])*g_rstd[c]*gamma[c] + beta[c];
            float g = gelu_f(y);
            int v = (int)rintf(g*scl);
            v = max(-128, min(127, v));
            packv |= ((unsigned int)(v & 0xFF)) << (8*j);
        }
        g_xq[(b*LL + l)*(CC/4) + cg] = packv;
    }
}

// ---------------------------------------------------------------------------
// K6: int8 ternary matmul (dp4a, exact) + dequant + GELU + residual
// ---------------------------------------------------------------------------
__global__ __launch_bounds__(256) void matmul_kernel(const float* __restrict__ xin,
                                                     float* __restrict__ out){
    const int tok0 = blockIdx.x*64;
    const int o0   = blockIdx.y*64;
    const int b    = tok0 >> 10;
    const int lbase = tok0 & (LL-1);
    const int tid = threadIdx.x;
    const int tx = tid & 15, ty = tid >> 4;

    __shared__ unsigned int xs[64][65];
    __shared__ unsigned int wsm[64][65];

    int acc[4][4];
    #pragma unroll
    for (int i=0;i<4;i++){
        #pragma unroll
        for (int j=0;j<4;j++) acc[i][j]=0;
    }

    for (int kc = 0; kc < 2; kc++){
        const int k0 = kc*64;
        for (int idx = tid; idx < 64*64; idx += 256){
            int t = idx >> 6, k = idx & 63;
            xs[t][k] = g_xq[(tok0 + t)*(CC/4) + k0 + k];
        }
        for (int idx = tid; idx < 64*64; idx += 256){
            int o = idx >> 6, k = idx & 63;
            wsm[o][k] = g_wq[(o0 + o)*(CC/4) + k0 + k];
        }
        __syncthreads();
        #pragma unroll 8
        for (int kk = 0; kk < 64; kk++){
            int xf[4], wf[4];
            #pragma unroll
            for (int j=0;j<4;j++) xf[j] = (int)xs[tx*4+j][kk];
            #pragma unroll
            for (int j=0;j<4;j++) wf[j] = (int)wsm[ty*4+j][kk];
            #pragma unroll
            for (int oo=0;oo<4;oo++){
                #pragma unroll
                for (int tt=0;tt<4;tt++)
                    acc[oo][tt] = __dp4a(xf[tt], wf[oo], acc[oo][tt]);
            }
        }
        __syncthreads();
    }

    const float wr = g_wrecip_d;
    float ar[4];
    #pragma unroll
    for (int tt=0;tt<4;tt++) ar[tt] = g_arecip[tok0 + tx*4 + tt];

    #pragma unroll
    for (int oo=0;oo<4;oo++){
        int o = o0 + ty*4 + oo;
        const float4 rx = *(const float4*)&xin[(b*CC + o)*LL + lbase + tx*4];
        float4 st;
        st.x = gelu_f((float)acc[oo][0]*ar[0]*wr) + rx.x;
        st.y = gelu_f((float)acc[oo][1]*ar[1]*wr) + rx.y;
        st.z = gelu_f((float)acc[oo][2]*ar[2]*wr) + rx.z;
        st.w = gelu_f((float)acc[oo][3]*ar[3]*wr) + rx.w;
        *(float4*)&out[(b*CC + o)*LL + lbase + tx*4] = st;
    }
}

// ---------------------------------------------------------------------------
extern "C" void kernel_launch(void* const* d_in, const int* in_sizes, int n_in,
                              void* d_out, int out_size){
    const float* x      = (const float*)d_in[0];
    const float* conv_w = (const float*)d_in[1];
    const float* conv_b = (const float*)d_in[2];
    const float* gamma  = (const float*)d_in[3];
    const float* beta   = (const float*)d_in[4];
    const float* proj_w = (const float*)d_in[5];
    float* out = (float*)d_out;

    static bool attr_done = false;
    if (!attr_done){
        cudaFuncSetAttribute(conv_mma_kernel,
                             cudaFuncAttributeMaxDynamicSharedMemorySize,
                             CONV_SMEM);
        attr_done = true;
    }

    prep_x_kernel<<<dim3(32,16,32), 256>>>(x);
    pad_x_kernel<<<128, 256>>>();
    prep_w_kernel<<<1024, 256>>>(conv_w);
    conv_mma_kernel<<<dim3(8,4,32), 256, CONV_SMEM>>>(conv_b);
    bnstats_kernel<<<512, 256>>>();
    wabs_kernel<<<1, 256>>>(proj_w);
    wpack_kernel<<<256, 256>>>(proj_w);
    quant_kernel<<<dim3(32,32), 256>>>(gamma, beta);
    matmul_kernel<<<dim3(512,8), 256>>>(x, out);
}